// round 7
// baseline (speedup 1.0000x reference)
#include <cuda_runtime.h>
#include <cuda_fp16.h>
#include <cstdint>
#include <cstring>

#define NTOK 3136
#define CCH  96
#define BB   128
#define KF   49
#define KSB  208   // smem row stride in bytes (13*16 -> conflict-free ldmatrix)

// fp16 impulse responses, one per (token, d). 602 KB scratch.
__device__ unsigned short g_H[NTOK * CCH];

// ---------------- main-kernel smem layout (bytes), total 46848 ----------------
#define SM_HH  0                        // 96 u16 (pad to 256)
#define SM_XH  256                      // 128 x 208 B = 26624
#define SM_BH  (SM_XH + BB * KSB)       // 26880: 96 x 208 B = 19968
#define SMEM_BYTES (SM_BH + CCH * KSB)  // 46848

__device__ __forceinline__ uint32_t smem_u32(const void* p) {
    uint32_t a;
    asm("{ .reg .u64 t; cvta.to.shared.u64 t, %1; cvt.u32.u64 %0, t; }"
        : "=r"(a) : "l"(p));
    return a;
}
__device__ __forceinline__ uint32_t h2_as_u32(__half2 h) {
    uint32_t u;
    memcpy(&u, &h, 4);
    return u;
}
__device__ __forceinline__ void ldsm_x4(uint32_t* r, uint32_t addr) {
    asm volatile("ldmatrix.sync.aligned.m8n8.x4.shared.b16 {%0,%1,%2,%3}, [%4];"
                 : "=r"(r[0]), "=r"(r[1]), "=r"(r[2]), "=r"(r[3]) : "r"(addr));
}
__device__ __forceinline__ void mma_fp16(float* c, const uint32_t* a,
                                         uint32_t b0, uint32_t b1) {
    asm volatile(
        "mma.sync.aligned.m16n8k16.row.col.f32.f16.f16.f32 "
        "{%0,%1,%2,%3}, {%4,%5,%6,%7}, {%8,%9}, {%0,%1,%2,%3};"
        : "+f"(c[0]), "+f"(c[1]), "+f"(c[2]), "+f"(c[3])
        : "r"(a[0]), "r"(a[1]), "r"(a[2]), "r"(a[3]), "r"(b0), "r"(b1));
}

// ---------------------------------------------------------------------------
// Kernel 1: DFT of w -> fp16 impulse response h. 4 tokens per 384-thread block.
// ---------------------------------------------------------------------------
__global__ void __launch_bounds__(384)
compute_h_kernel(const float* __restrict__ w) {
    __shared__ float wc[4 * 98];
    __shared__ float ct[CCH], st[CCH];
    const int t = threadIdx.x;

    for (int i = t; i < 4 * 98; i += 384)
        wc[i] = w[(size_t)blockIdx.x * 392 + i];
    if (t < CCH) {
        float s, c;
        sincosf((float)t * (6.283185307179586f / 96.0f), &s, &c);
        ct[t] = c;
        st[t] = s;
    }
    __syncthreads();

    const int tok = t / CCH;
    const int d   = t - tok * CCH;
    const float* wp = wc + tok * 98;

    float acc = wp[0] + ((d & 1) ? -wp[96] : wp[96]);
    // two independent partial chains to halve serial-FMA latency
    float s0 = 0.0f, s1 = 0.0f;
    int m0 = 0, m1 = d;  // m for k and k+1
#pragma unroll 2
    for (int k = 1; k < 48; k += 2) {
        m0 += d; if (m0 >= CCH) m0 -= CCH;
        s0 = fmaf(wp[2 * k], ct[m0], s0);
        s0 = fmaf(-wp[2 * k + 1], st[m0], s0);
        m1 += d; if (m1 >= CCH) m1 -= CCH;
        if (k + 1 < 48) {
            s1 = fmaf(wp[2 * (k + 1)], ct[m1], s1);
            s1 = fmaf(-wp[2 * (k + 1) + 1], st[m1], s1);
        }
        m1 += d; if (m1 >= CCH) m1 -= CCH;
        m0 += d; if (m0 >= CCH) m0 -= CCH;
    }
    float hv = (acc + 2.0f * (s0 + s1)) * (1.0f / 96.0f);
    g_H[(size_t)(blockIdx.x * 4 + tok) * CCH + d] = __half_as_ushort(__float2half_rn(hv));
}

// ---------------------------------------------------------------------------
// Kernel 2: per token n, Y[128,96] = X_fp16[128,96] * B[96,96]^T
// with B[row][k] = h[(row-k) mod 96], fp16 inputs, fp32 accumulation.
// ---------------------------------------------------------------------------
extern __shared__ unsigned char smem_raw[];

__global__ void __launch_bounds__(256, 4)
gf_hmma_kernel(const float* __restrict__ x, float* __restrict__ out) {
    const int tid = threadIdx.x;
    const int n   = blockIdx.x;
    const size_t NC   = (size_t)NTOK * CCH;
    const size_t xoff = (size_t)n * CCH;

    // ---- phase 1: load h (as u32 pairs); stage X -> fp16 in smem ----
    if (tid < 48) {
        const uint32_t* gh = (const uint32_t*)(g_H + (size_t)n * CCH);
        ((uint32_t*)(smem_raw + SM_HH))[tid] = gh[tid];
    }

    // X: 128 rows x 12 float8-chunks; 6 iterations x 256 threads
#pragma unroll
    for (int it = 0; it < 6; it++) {
        int idx = tid + it * 256;            // 0..1535
        int row = idx / 12, c8 = idx % 12;
        const float4* src = (const float4*)(x + (size_t)row * NC + xoff + (size_t)(c8 * 8));
        float4 v0 = src[0];
        float4 v1 = src[1];
        uint4 o;
        o.x = h2_as_u32(__floats2half2_rn(v0.x, v0.y));
        o.y = h2_as_u32(__floats2half2_rn(v0.z, v0.w));
        o.z = h2_as_u32(__floats2half2_rn(v1.x, v1.y));
        o.w = h2_as_u32(__floats2half2_rn(v1.z, v1.w));
        *(uint4*)(smem_raw + SM_XH + (uint32_t)(row * KSB + c8 * 16)) = o;
    }
    __syncthreads();

    // ---- phase 2: build circulant B[row][k] = h[(row-k) mod 96] ----
    {
        const unsigned short* hh = (const unsigned short*)(smem_raw + SM_HH);
#pragma unroll 2
        for (int i = tid; i < CCH * 48; i += 256) {
            int row = i / 48;
            int p   = i - row * 48;
            int m0 = row - 2 * p; if (m0 < 0) m0 += CCH;
            int m1 = m0 - 1;      if (m1 < 0) m1 += CCH;
            uint32_t vh = (uint32_t)hh[m0] | ((uint32_t)hh[m1] << 16);
            *(uint32_t*)(smem_raw + SM_BH + (uint32_t)(row * KSB + p * 4)) = vh;
        }
    }
    __syncthreads();

    // ---- phase 3: MMA. warp owns 32 rows x 48 cols; m-split halves ----
    const int wid  = tid >> 5;
    const int lane = tid & 31;
    const int m0   = (wid & 3) * 32;
    const int n0   = (wid >> 2) * 48;

    const uint32_t base  = smem_u32(smem_raw);
    const int lrow  = lane & 15;
    const int lhalf = (lane >> 4) << 4;

    const uint32_t b_b = base + SM_BH + (uint32_t)((n0 + lrow) * KSB) + lhalf;

#pragma unroll
    for (int mh = 0; mh < 2; mh++) {
        const uint32_t a_h = base + SM_XH
                           + (uint32_t)((m0 + mh * 16 + lrow) * KSB) + lhalf;
        float acc[6][4];
#pragma unroll
        for (int nt = 0; nt < 6; nt++)
#pragma unroll
            for (int q = 0; q < 4; q++) acc[nt][q] = 0.0f;

#pragma unroll
        for (int ks = 0; ks < 6; ks++) {
            const uint32_t koff = (uint32_t)(ks * 32);
            uint32_t a[4], b0[4], b1[4], b2[4];
            ldsm_x4(a,  a_h + koff);
            ldsm_x4(b0, b_b + koff);
            ldsm_x4(b1, b_b + koff + 16 * KSB);
            ldsm_x4(b2, b_b + koff + 32 * KSB);
            mma_fp16(acc[0], a, b0[0], b0[2]);
            mma_fp16(acc[1], a, b0[1], b0[3]);
            mma_fp16(acc[2], a, b1[0], b1[2]);
            mma_fp16(acc[3], a, b1[1], b1[3]);
            mma_fp16(acc[4], a, b2[0], b2[2]);
            mma_fp16(acc[5], a, b2[1], b2[3]);
        }

        // epilogue for this m-half
        const int rbase = m0 + mh * 16 + (lane >> 2);
        const int cb    = n0 + (lane & 3) * 2;
        float* o0 = out + (size_t)rbase * NC + xoff;
        float* o1 = o0 + 8 * NC;
#pragma unroll
        for (int nt = 0; nt < 6; nt++) {
            const int col = cb + nt * 8;
            *(float2*)(o0 + col) = make_float2(acc[nt][0], acc[nt][1]);
            *(float2*)(o1 + col) = make_float2(acc[nt][2], acc[nt][3]);
        }
    }
}

// ---------------------------------------------------------------------------
extern "C" void kernel_launch(void* const* d_in, const int* in_sizes, int n_in,
                              void* d_out, int out_size) {
    const float* x = (const float*)d_in[0];   // [B, N, C] f32
    const float* w = (const float*)d_in[1];   // [N, 49, 2] f32
    float* out = (float*)d_out;

    compute_h_kernel<<<NTOK / 4, 384>>>(w);

    cudaFuncSetAttribute(gf_hmma_kernel,
                         cudaFuncAttributeMaxDynamicSharedMemorySize, SMEM_BYTES);
    gf_hmma_kernel<<<NTOK, 256, SMEM_BYTES>>>(x, out);
}

// round 9
// speedup vs baseline: 1.2790x; 1.2790x over previous
#include <cuda_runtime.h>
#include <cuda_fp16.h>
#include <cstdint>
#include <cstring>

#define NTOK 3136
#define CCH  96
#define BB   128
#define KF   49
#define KSB  208   // smem row stride in bytes (13*16 -> conflict-free ldmatrix)
#define OSW  104   // out-staging row stride in floats (==8 mod 32 -> conflict-free)

// fp16 impulse responses, one per (token, d). 602 KB scratch.
__device__ unsigned short g_H[NTOK * CCH];

// ---------------- main-kernel smem layout (bytes) ----------------
// Phase A (staging+MMA): HH 0..256, XH 256..26880, BH 26880..46848
// Phase B (epilogue): entire buffer reused as 128 x 104 f32 staging (53248 B)
#define SM_HH  0
#define SM_XH  256
#define SM_BH  (SM_XH + BB * KSB)          // 26880
#define SMEM_BYTES (BB * OSW * 4)          // 53248 (> 46848 phase-A need)

__device__ __forceinline__ uint32_t smem_u32(const void* p) {
    uint32_t a;
    asm("{ .reg .u64 t; cvta.to.shared.u64 t, %1; cvt.u32.u64 %0, t; }"
        : "=r"(a) : "l"(p));
    return a;
}
__device__ __forceinline__ uint32_t h2_as_u32(__half2 h) {
    uint32_t u;
    memcpy(&u, &h, 4);
    return u;
}
__device__ __forceinline__ void ldsm_x4(uint32_t* r, uint32_t addr) {
    asm volatile("ldmatrix.sync.aligned.m8n8.x4.shared.b16 {%0,%1,%2,%3}, [%4];"
                 : "=r"(r[0]), "=r"(r[1]), "=r"(r[2]), "=r"(r[3]) : "r"(addr));
}
__device__ __forceinline__ void mma_fp16(float* c, const uint32_t* a,
                                         uint32_t b0, uint32_t b1) {
    asm volatile(
        "mma.sync.aligned.m16n8k16.row.col.f32.f16.f16.f32 "
        "{%0,%1,%2,%3}, {%4,%5,%6,%7}, {%8,%9}, {%0,%1,%2,%3};"
        : "+f"(c[0]), "+f"(c[1]), "+f"(c[2]), "+f"(c[3])
        : "r"(a[0]), "r"(a[1]), "r"(a[2]), "r"(a[3]), "r"(b0), "r"(b1));
}

// ---------------------------------------------------------------------------
// Kernel 1: DFT of w -> fp16 impulse response h. 4 tokens per 384-thread block.
// ---------------------------------------------------------------------------
__global__ void __launch_bounds__(384)
compute_h_kernel(const float* __restrict__ w) {
    __shared__ float wc[4 * 98];
    __shared__ float ct[CCH], st[CCH];
    const int t = threadIdx.x;

    for (int i = t; i < 4 * 98; i += 384)
        wc[i] = w[(size_t)blockIdx.x * 392 + i];
    if (t < CCH) {
        float s, c;
        sincosf((float)t * (6.283185307179586f / 96.0f), &s, &c);
        ct[t] = c;
        st[t] = s;
    }
    __syncthreads();

    const int tok = t / CCH;
    const int d   = t - tok * CCH;
    const float* wp = wc + tok * 98;

    float acc = wp[0] + ((d & 1) ? -wp[96] : wp[96]);
    float s0 = 0.0f, s1 = 0.0f;
    int m0 = 0, m1 = d;
#pragma unroll 2
    for (int k = 1; k < 48; k += 2) {
        m0 += d; if (m0 >= CCH) m0 -= CCH;
        s0 = fmaf(wp[2 * k], ct[m0], s0);
        s0 = fmaf(-wp[2 * k + 1], st[m0], s0);
        m1 += d; if (m1 >= CCH) m1 -= CCH;
        if (k + 1 < 48) {
            s1 = fmaf(wp[2 * (k + 1)], ct[m1], s1);
            s1 = fmaf(-wp[2 * (k + 1) + 1], st[m1], s1);
        }
        m1 += d; if (m1 >= CCH) m1 -= CCH;
        m0 += d; if (m0 >= CCH) m0 -= CCH;
    }
    float hv = (acc + 2.0f * (s0 + s1)) * (1.0f / 96.0f);
    g_H[(size_t)(blockIdx.x * 4 + tok) * CCH + d] = __half_as_ushort(__float2half_rn(hv));
}

// ---------------------------------------------------------------------------
// Kernel 2: per token n, Y[128,96] = X_fp16[128,96] * B[96,96]^T,
// B[row][k] = h[(row-k) mod 96]; fp16 inputs, fp32 accum; staged epilogue.
// ---------------------------------------------------------------------------
extern __shared__ unsigned char smem_raw[];

__global__ void __launch_bounds__(256, 3)
gf_hmma_kernel(const float* __restrict__ x, float* __restrict__ out) {
    const int tid = threadIdx.x;
    const int n   = blockIdx.x;
    const size_t NC   = (size_t)NTOK * CCH;
    const size_t xoff = (size_t)n * CCH;

    // ---- phase 1: load h; stage X -> fp16 in smem ----
    if (tid < 48) {
        const uint32_t* gh = (const uint32_t*)(g_H + (size_t)n * CCH);
        ((uint32_t*)(smem_raw + SM_HH))[tid] = gh[tid];
    }
#pragma unroll
    for (int it = 0; it < 6; it++) {
        int idx = tid + it * 256;            // 0..1535
        int row = idx / 12, c8 = idx % 12;
        const float4* src = (const float4*)(x + (size_t)row * NC + xoff + (size_t)(c8 * 8));
        float4 v0 = src[0];
        float4 v1 = src[1];
        uint4 o;
        o.x = h2_as_u32(__floats2half2_rn(v0.x, v0.y));
        o.y = h2_as_u32(__floats2half2_rn(v0.z, v0.w));
        o.z = h2_as_u32(__floats2half2_rn(v1.x, v1.y));
        o.w = h2_as_u32(__floats2half2_rn(v1.z, v1.w));
        *(uint4*)(smem_raw + SM_XH + (uint32_t)(row * KSB + c8 * 16)) = o;
    }
    __syncthreads();

    // ---- phase 2: circulant B build, rotation indexing (no div/mod) ----
    if (tid < 192) {
        const unsigned short* hh = (const unsigned short*)(smem_raw + SM_HH);
        const int row  = tid >> 1;
        const int half = tid & 1;
        // pair p covers k = 2p, 2p+1; value = (hh[m], hh[m-1]), m = (row-2p) mod 96
        // start p = half*24  ->  m = row - 48*half (mod 96)
        int m = row - 48 * half; if (m < 0) m += CCH;
        uint32_t addr = (uint32_t)(row * KSB + half * 96);
        unsigned char* bp = smem_raw + SM_BH;
#pragma unroll
        for (int p = 0; p < 24; p++) {
            int m1 = m - 1; if (m1 < 0) m1 += CCH;
            *(uint32_t*)(bp + addr) = (uint32_t)hh[m] | ((uint32_t)hh[m1] << 16);
            addr += 4;
            m -= 2; if (m < 0) m += CCH;
        }
    }
    __syncthreads();

    // ---- phase 3: MMA. warp = 32 rows x 48 cols; B loaded once per ks ----
    const int wid  = tid >> 5;
    const int lane = tid & 31;
    const int m0   = (wid & 3) * 32;
    const int n0   = (wid >> 2) * 48;

    const uint32_t base  = smem_u32(smem_raw);
    const int lrow  = lane & 15;
    const int lhalf = (lane >> 4) << 4;

    const uint32_t a_b = base + SM_XH + (uint32_t)((m0 + lrow) * KSB) + lhalf;
    const uint32_t b_b = base + SM_BH + (uint32_t)((n0 + lrow) * KSB) + lhalf;

    float acc[2][6][4];
#pragma unroll
    for (int mh = 0; mh < 2; mh++)
#pragma unroll
        for (int nt = 0; nt < 6; nt++)
#pragma unroll
            for (int q = 0; q < 4; q++) acc[mh][nt][q] = 0.0f;

#pragma unroll
    for (int ks = 0; ks < 6; ks++) {
        const uint32_t koff = (uint32_t)(ks * 32);
        uint32_t b0[4], b1[4], b2[4], a0[4], a1[4];
        ldsm_x4(b0, b_b + koff);
        ldsm_x4(b1, b_b + koff + 16 * KSB);
        ldsm_x4(b2, b_b + koff + 32 * KSB);
        ldsm_x4(a0, a_b + koff);
        ldsm_x4(a1, a_b + koff + 16 * KSB);
        mma_fp16(acc[0][0], a0, b0[0], b0[2]);
        mma_fp16(acc[0][1], a0, b0[1], b0[3]);
        mma_fp16(acc[0][2], a0, b1[0], b1[2]);
        mma_fp16(acc[0][3], a0, b1[1], b1[3]);
        mma_fp16(acc[0][4], a0, b2[0], b2[2]);
        mma_fp16(acc[0][5], a0, b2[1], b2[3]);
        mma_fp16(acc[1][0], a1, b0[0], b0[2]);
        mma_fp16(acc[1][1], a1, b0[1], b0[3]);
        mma_fp16(acc[1][2], a1, b1[0], b1[2]);
        mma_fp16(acc[1][3], a1, b1[1], b1[3]);
        mma_fp16(acc[1][4], a1, b2[0], b2[2]);
        mma_fp16(acc[1][5], a1, b2[1], b2[3]);
    }

    // ---- phase 4: staged epilogue ----
    __syncthreads();   // all LDSM reads done; smem becomes staging buffer
    {
        float* stg = (float*)smem_raw;
        const int rb = m0 + (lane >> 2);
        const int cb = n0 + (lane & 3) * 2;
#pragma unroll
        for (int mh = 0; mh < 2; mh++) {
            const int r0 = rb + mh * 16;
#pragma unroll
            for (int nt = 0; nt < 6; nt++) {
                const int col = cb + nt * 8;
                *(float2*)(stg + r0 * OSW + col)       = make_float2(acc[mh][nt][0], acc[mh][nt][1]);
                *(float2*)(stg + (r0 + 8) * OSW + col) = make_float2(acc[mh][nt][2], acc[mh][nt][3]);
            }
        }
    }
    __syncthreads();
    {
        const float* stg = (const float*)smem_raw;
#pragma unroll
        for (int i = 0; i < 12; i++) {
            int g   = tid + i * 256;          // 0..3071
            int row = g / 24, c4 = (g % 24) * 4;
            float4 v = *(const float4*)(stg + row * OSW + c4);
            *(float4*)(out + (size_t)row * NC + xoff + c4) = v;
        }
    }
}

// ---------------------------------------------------------------------------
extern "C" void kernel_launch(void* const* d_in, const int* in_sizes, int n_in,
                              void* d_out, int out_size) {
    const float* x = (const float*)d_in[0];   // [B, N, C] f32
    const float* w = (const float*)d_in[1];   // [N, 49, 2] f32
    float* out = (float*)d_out;

    compute_h_kernel<<<NTOK / 4, 384>>>(w);

    cudaFuncSetAttribute(gf_hmma_kernel,
                         cudaFuncAttributeMaxDynamicSharedMemorySize, SMEM_BYTES);
    gf_hmma_kernel<<<NTOK, 256, SMEM_BYTES>>>(x, out);
}

// round 10
// speedup vs baseline: 1.4700x; 1.1493x over previous
#include <cuda_runtime.h>
#include <cuda_fp16.h>
#include <cstdint>
#include <cstring>

#define NTOK 3136
#define CCH  96
#define BB   128
#define KSB  208   // smem row stride in bytes (13*16 -> conflict-free ldmatrix)
#define OSW  104   // out-staging row stride in floats (==8 mod 32 -> conflict-free)

// ---------------- smem layout (bytes) ----------------
// Phase A: HH 0..256, WC 256..768, XH 768..27392, BH 27392..47360
// Phase B (epilogue): whole buffer reused as 128 x 104 f32 staging (53248 B)
#define SM_HH  0
#define SM_WC  256
#define SM_XH  768
#define SM_BH  (SM_XH + BB * KSB)          // 27392
#define SMEM_BYTES (BB * OSW * 4)          // 53248 (> 47360 phase-A need)

__device__ __forceinline__ uint32_t smem_u32(const void* p) {
    uint32_t a;
    asm("{ .reg .u64 t; cvta.to.shared.u64 t, %1; cvt.u32.u64 %0, t; }"
        : "=r"(a) : "l"(p));
    return a;
}
__device__ __forceinline__ uint32_t h2_as_u32(__half2 h) {
    uint32_t u;
    memcpy(&u, &h, 4);
    return u;
}
__device__ __forceinline__ void ldsm_x4(uint32_t* r, uint32_t addr) {
    asm volatile("ldmatrix.sync.aligned.m8n8.x4.shared.b16 {%0,%1,%2,%3}, [%4];"
                 : "=r"(r[0]), "=r"(r[1]), "=r"(r[2]), "=r"(r[3]) : "r"(addr));
}
__device__ __forceinline__ void mma_fp16(float* c, const uint32_t* a,
                                         uint32_t b0, uint32_t b1) {
    asm volatile(
        "mma.sync.aligned.m16n8k16.row.col.f32.f16.f16.f32 "
        "{%0,%1,%2,%3}, {%4,%5,%6,%7}, {%8,%9}, {%0,%1,%2,%3};"
        : "+f"(c[0]), "+f"(c[1]), "+f"(c[2]), "+f"(c[3])
        : "r"(a[0]), "r"(a[1]), "r"(a[2]), "r"(a[3]), "r"(b0), "r"(b1));
}

// ---------------------------------------------------------------------------
// Fused kernel: per token n,
//   h[d] = (1/96)[Re w0 + (-1)^d Re w48 + 2*sum_{k=1..47}(Re wk cos - Im wk sin)]
//   Y[128,96] = X_fp16[128,96] * B[96,96]^T,  B[row][k] = h[(row-k) mod 96]
// ---------------------------------------------------------------------------
extern __shared__ unsigned char smem_raw[];

__global__ void __launch_bounds__(256, 3)
gf_fused_kernel(const float* __restrict__ x, const float* __restrict__ w,
                float* __restrict__ out) {
    const int tid = threadIdx.x;
    const int n   = blockIdx.x;
    const size_t NC   = (size_t)NTOK * CCH;
    const size_t xoff = (size_t)n * CCH;

    // ---- phase 1: stage X -> fp16 smem; stage w -> smem ----
    float wcv = 0.0f;
    if (tid < 98) wcv = w[(size_t)n * 98 + tid];

#pragma unroll
    for (int it = 0; it < 6; it++) {
        int idx = tid + it * 256;            // 0..1535
        int row = idx / 12, c8 = idx % 12;
        const float4* src = (const float4*)(x + (size_t)row * NC + xoff + (size_t)(c8 * 8));
        float4 v0 = src[0];
        float4 v1 = src[1];
        uint4 o;
        o.x = h2_as_u32(__floats2half2_rn(v0.x, v0.y));
        o.y = h2_as_u32(__floats2half2_rn(v0.z, v0.w));
        o.z = h2_as_u32(__floats2half2_rn(v1.x, v1.y));
        o.w = h2_as_u32(__floats2half2_rn(v1.z, v1.w));
        *(uint4*)(smem_raw + SM_XH + (uint32_t)(row * KSB + c8 * 16)) = o;
    }
    if (tid < 98) ((float*)(smem_raw + SM_WC))[tid] = wcv;
    __syncthreads();

    // ---- phase 2: DFT -> h[d] (threads 0..95), twiddle recurrence ----
    if (tid < CCH) {
        const float* wp = (const float*)(smem_raw + SM_WC);   // wp[2k]=re, wp[2k+1]=im
        const int d = tid;
        float c1, s1;
        __sincosf((float)d * (6.283185307179586f / 96.0f), &s1, &c1);
        float acc = wp[0] + ((d & 1) ? -wp[96] : wp[96]);
        float c = c1, s = s1;
        float sum = 0.0f;
#pragma unroll 4
        for (int k = 1; k < 48; k++) {
            sum = fmaf(wp[2 * k], c, sum);
            sum = fmaf(-wp[2 * k + 1], s, sum);
            float cn = fmaf(c, c1, -s * s1);
            float sn = fmaf(s, c1,  c * s1);
            c = cn; s = sn;
        }
        float hv = (acc + 2.0f * sum) * (1.0f / 96.0f);
        ((unsigned short*)(smem_raw + SM_HH))[d] =
            __half_as_ushort(__float2half_rn(hv));
    }
    __syncthreads();

    // ---- phase 3: circulant B build, rotation indexing (no div/mod) ----
    if (tid < 192) {
        const unsigned short* hh = (const unsigned short*)(smem_raw + SM_HH);
        const int row  = tid >> 1;
        const int half = tid & 1;
        // pair p covers k = 2p, 2p+1; value = (hh[m], hh[m-1]), m = (row-2p) mod 96
        int m = row - 48 * half; if (m < 0) m += CCH;
        uint32_t addr = (uint32_t)(row * KSB + half * 96);
        unsigned char* bp = smem_raw + SM_BH;
#pragma unroll
        for (int p = 0; p < 24; p++) {
            int m1 = m - 1; if (m1 < 0) m1 += CCH;
            *(uint32_t*)(bp + addr) = (uint32_t)hh[m] | ((uint32_t)hh[m1] << 16);
            addr += 4;
            m -= 2; if (m < 0) m += CCH;
        }
    }
    __syncthreads();

    // ---- phase 4: MMA. warp = 32 rows x 48 cols; B loaded once per ks ----
    const int wid  = tid >> 5;
    const int lane = tid & 31;
    const int m0   = (wid & 3) * 32;
    const int n0   = (wid >> 2) * 48;

    const uint32_t base  = smem_u32(smem_raw);
    const int lrow  = lane & 15;
    const int lhalf = (lane >> 4) << 4;

    const uint32_t a_b = base + SM_XH + (uint32_t)((m0 + lrow) * KSB) + lhalf;
    const uint32_t b_b = base + SM_BH + (uint32_t)((n0 + lrow) * KSB) + lhalf;

    float acc[2][6][4];
#pragma unroll
    for (int mh = 0; mh < 2; mh++)
#pragma unroll
        for (int nt = 0; nt < 6; nt++)
#pragma unroll
            for (int q = 0; q < 4; q++) acc[mh][nt][q] = 0.0f;

#pragma unroll
    for (int ks = 0; ks < 6; ks++) {
        const uint32_t koff = (uint32_t)(ks * 32);
        uint32_t b0[4], b1[4], b2[4], a0[4], a1[4];
        ldsm_x4(b0, b_b + koff);
        ldsm_x4(b1, b_b + koff + 16 * KSB);
        ldsm_x4(b2, b_b + koff + 32 * KSB);
        ldsm_x4(a0, a_b + koff);
        ldsm_x4(a1, a_b + koff + 16 * KSB);
        mma_fp16(acc[0][0], a0, b0[0], b0[2]);
        mma_fp16(acc[0][1], a0, b0[1], b0[3]);
        mma_fp16(acc[0][2], a0, b1[0], b1[2]);
        mma_fp16(acc[0][3], a0, b1[1], b1[3]);
        mma_fp16(acc[0][4], a0, b2[0], b2[2]);
        mma_fp16(acc[0][5], a0, b2[1], b2[3]);
        mma_fp16(acc[1][0], a1, b0[0], b0[2]);
        mma_fp16(acc[1][1], a1, b0[1], b0[3]);
        mma_fp16(acc[1][2], a1, b1[0], b1[2]);
        mma_fp16(acc[1][3], a1, b1[1], b1[3]);
        mma_fp16(acc[1][4], a1, b2[0], b2[2]);
        mma_fp16(acc[1][5], a1, b2[1], b2[3]);
    }

    // ---- phase 5: staged epilogue ----
    __syncthreads();   // all LDSM reads done; smem becomes staging buffer
    {
        float* stg = (float*)smem_raw;
        const int rb = m0 + (lane >> 2);
        const int cb = n0 + (lane & 3) * 2;
#pragma unroll
        for (int mh = 0; mh < 2; mh++) {
            const int r0 = rb + mh * 16;
#pragma unroll
            for (int nt = 0; nt < 6; nt++) {
                const int col = cb + nt * 8;
                *(float2*)(stg + r0 * OSW + col)       = make_float2(acc[mh][nt][0], acc[mh][nt][1]);
                *(float2*)(stg + (r0 + 8) * OSW + col) = make_float2(acc[mh][nt][2], acc[mh][nt][3]);
            }
        }
    }
    __syncthreads();
    {
        const float* stg = (const float*)smem_raw;
#pragma unroll
        for (int i = 0; i < 12; i++) {
            int g   = tid + i * 256;          // 0..3071
            int row = g / 24, c4 = (g % 24) * 4;
            float4 v = *(const float4*)(stg + row * OSW + c4);
            *(float4*)(out + (size_t)row * NC + xoff + c4) = v;
        }
    }
}

// ---------------------------------------------------------------------------
extern "C" void kernel_launch(void* const* d_in, const int* in_sizes, int n_in,
                              void* d_out, int out_size) {
    const float* x = (const float*)d_in[0];   // [B, N, C] f32
    const float* w = (const float*)d_in[1];   // [N, 49, 2] f32
    float* out = (float*)d_out;

    cudaFuncSetAttribute(gf_fused_kernel,
                         cudaFuncAttributeMaxDynamicSharedMemorySize, SMEM_BYTES);
    gf_fused_kernel<<<NTOK, 256, SMEM_BYTES>>>(x, w, out);
}